// round 1
// baseline (speedup 1.0000x reference)
#include <cuda_runtime.h>
#include <cstdint>
#include <cstdio>

// Problem constants
#define PB 2
#define PS 2048
#define PD 2048
#define PH 32
#define PKV 8
#define PHD 64
#define PM (PB * PS)          // 4096 rows of x
#define PG (PH / PKV)         // 4

// ---------------------------------------------------------------------------
// Scratch (device globals; no runtime allocation allowed)
// ---------------------------------------------------------------------------
__device__ float g_Q[(size_t)PM * PD];             // (4096, 2048)  32MB
__device__ float g_K[(size_t)PM * (PKV * PHD)];    // (4096, 512)    8MB
__device__ float g_V[(size_t)PM * (PKV * PHD)];    // (4096, 512)    8MB
__device__ float g_AO[(size_t)PM * PD];            // (4096, 2048)  32MB

// ---------------------------------------------------------------------------
// SGEMM (NT): C[M,N] = A[M,K] @ B[N,K]^T    (all row-major, K contiguous)
// 128x128 tile, BK=16, 256 threads, 8x8 per thread (split 4+4 rows/cols)
// ---------------------------------------------------------------------------
#define GBM 128
#define GBN 128
#define GBK 16
#define GPAD 132   // keeps 16B alignment per k-row; 2-way max bank conflicts

__global__ __launch_bounds__(256, 2)
void sgemm_nt(const float* __restrict__ A, const float* __restrict__ B,
              float* __restrict__ C, int M, int N, int K)
{
    __shared__ float As[GBK][GPAD];   // stored transposed: As[k][m]
    __shared__ float Bs[GBK][GPAD];   // Bs[k][n]

    const int tid = threadIdx.x;
    const int tx = tid & 15;
    const int ty = tid >> 4;
    const int bm = blockIdx.y;
    const int bn = blockIdx.x;

    const float* Ab = A + (size_t)bm * GBM * K;
    const float* Bb = B + (size_t)bn * GBN * K;

    float acc[8][8];
#pragma unroll
    for (int i = 0; i < 8; i++)
#pragma unroll
        for (int j = 0; j < 8; j++) acc[i][j] = 0.f;

    for (int k0 = 0; k0 < K; k0 += GBK) {
        // load 128x16 tiles of A and B (2 float4 per thread each), transpose into smem
#pragma unroll
        for (int r = 0; r < 2; r++) {
            int e   = tid + 256 * r;          // 0..511
            int row = e >> 2;                 // 0..127
            int ks  = (e & 3) << 2;           // 0,4,8,12
            float4 va = *(const float4*)(Ab + (size_t)row * K + k0 + ks);
            As[ks + 0][row] = va.x; As[ks + 1][row] = va.y;
            As[ks + 2][row] = va.z; As[ks + 3][row] = va.w;
            float4 vb = *(const float4*)(Bb + (size_t)row * K + k0 + ks);
            Bs[ks + 0][row] = vb.x; Bs[ks + 1][row] = vb.y;
            Bs[ks + 2][row] = vb.z; Bs[ks + 3][row] = vb.w;
        }
        __syncthreads();

#pragma unroll
        for (int kk = 0; kk < GBK; kk++) {
            float a[8], b[8];
            float4 t;
            t = *(const float4*)&As[kk][ty << 2];        a[0]=t.x; a[1]=t.y; a[2]=t.z; a[3]=t.w;
            t = *(const float4*)&As[kk][64 + (ty << 2)]; a[4]=t.x; a[5]=t.y; a[6]=t.z; a[7]=t.w;
            t = *(const float4*)&Bs[kk][tx << 2];        b[0]=t.x; b[1]=t.y; b[2]=t.z; b[3]=t.w;
            t = *(const float4*)&Bs[kk][64 + (tx << 2)]; b[4]=t.x; b[5]=t.y; b[6]=t.z; b[7]=t.w;
#pragma unroll
            for (int i = 0; i < 8; i++)
#pragma unroll
                for (int j = 0; j < 8; j++) acc[i][j] += a[i] * b[j];
        }
        __syncthreads();
    }

    // epilogue: rows {4ty..4ty+3, 64+4ty..}, cols {4tx.., 64+4tx..}
#pragma unroll
    for (int i = 0; i < 8; i++) {
        int row = bm * GBM + ((i < 4) ? (ty * 4 + i) : (64 + ty * 4 + (i - 4)));
        float* Cr = C + (size_t)row * N + bn * GBN;
        float4 v0 = make_float4(acc[i][0], acc[i][1], acc[i][2], acc[i][3]);
        float4 v1 = make_float4(acc[i][4], acc[i][5], acc[i][6], acc[i][7]);
        *(float4*)(Cr + (tx << 2))      = v0;
        *(float4*)(Cr + 64 + (tx << 2)) = v1;
    }
}

// ---------------------------------------------------------------------------
// RoPE (in place).  X viewed as (PM, nheads, 64); pairs (d, d+32), d<32.
// cos/sin: (S, 32)
// ---------------------------------------------------------------------------
__global__ void rope_kernel(float* __restrict__ X, const float* __restrict__ cs,
                            const float* __restrict__ sn, int nheads)
{
    int i = blockIdx.x * blockDim.x + threadIdx.x;
    int total = PM * nheads * 32;
    if (i >= total) return;
    int d   = i & 31;
    int h   = (i >> 5) % nheads;
    int row = i / (32 * nheads);
    int s   = row & (PS - 1);
    float c = cs[s * 32 + d];
    float sv = sn[s * 32 + d];
    float* base = X + ((size_t)row * nheads + h) * 64;
    float x1 = base[d];
    float x2 = base[d + 32];
    base[d]      = x1 * c - x2 * sv;
    base[d + 32] = x1 * sv + x2 * c;
}

// ---------------------------------------------------------------------------
// Causal flash attention, fp32.
// grid (S/64, H, B), 256 threads (16x16), 64 queries x 64 keys per tile.
// Each thread owns a 4x4 tile of the 64x64 score matrix and of the output.
// smem: Qt[d][m] (pad 65), KtPs (K tile transposed, reused as P), Vs[n][d] (pad 68)
// ---------------------------------------------------------------------------
#define QP 65
#define VP 68
#define FA_SMEM ((2 * 64 * QP + 64 * VP + 3 * 64) * 4)

__global__ __launch_bounds__(256, 3)
void flash_attn(const float* __restrict__ Q, const float* __restrict__ Kg,
                const float* __restrict__ Vg, float* __restrict__ AO)
{
    extern __shared__ float sm[];
    float* Qt    = sm;                   // 64*65, layout [d][m]
    float* KtPs  = Qt + 64 * QP;         // 64*65, K tile [d][n] then P [m][n]
    float* Vs    = KtPs + 64 * QP;       // 64*68, layout [n][d]
    float* row_m = Vs + 64 * VP;
    float* row_l = row_m + 64;
    float* row_a = row_l + 64;

    const int qt = blockIdx.x;
    const int h  = blockIdx.y;
    const int b  = blockIdx.z;
    const int kvh = h >> 2;              // G = 4
    const int tid = threadIdx.x;
    const int tx = tid & 15;
    const int ty = tid >> 4;

    // Q base: (b, s=qt*64.., h, :)  row stride = PH*PHD = 2048
    const float* Qbase = Q + ((size_t)(b * PS + qt * 64)) * (PH * PHD) + h * PHD;

    // load Q tile transposed
#pragma unroll
    for (int r = 0; r < 4; r++) {
        int e   = tid + 256 * r;
        int row = e >> 4;
        int ds  = (e & 15) << 2;
        float4 v = *(const float4*)(Qbase + (size_t)row * (PH * PHD) + ds);
        Qt[(ds + 0) * QP + row] = v.x;
        Qt[(ds + 1) * QP + row] = v.y;
        Qt[(ds + 2) * QP + row] = v.z;
        Qt[(ds + 3) * QP + row] = v.w;
    }
    if (tid < 64) { row_m[tid] = -1e30f; row_l[tid] = 0.f; }

    float o[4][4];
#pragma unroll
    for (int i = 0; i < 4; i++)
#pragma unroll
        for (int j = 0; j < 4; j++) o[i][j] = 0.f;

    for (int kt = 0; kt <= qt; kt++) {
        const float* Kbase = Kg + ((size_t)(b * PS + kt * 64)) * (PKV * PHD) + kvh * PHD;
        const float* Vbase = Vg + ((size_t)(b * PS + kt * 64)) * (PKV * PHD) + kvh * PHD;

        __syncthreads();   // prior-iteration P/V reads done (also Q stores on iter 0)

        // load K tile transposed, V tile natural
#pragma unroll
        for (int r = 0; r < 4; r++) {
            int e   = tid + 256 * r;
            int row = e >> 4;
            int ds  = (e & 15) << 2;
            float4 kv4 = *(const float4*)(Kbase + (size_t)row * (PKV * PHD) + ds);
            KtPs[(ds + 0) * QP + row] = kv4.x;
            KtPs[(ds + 1) * QP + row] = kv4.y;
            KtPs[(ds + 2) * QP + row] = kv4.z;
            KtPs[(ds + 3) * QP + row] = kv4.w;
            float4 vv4 = *(const float4*)(Vbase + (size_t)row * (PKV * PHD) + ds);
            *(float4*)&Vs[row * VP + ds] = vv4;
        }
        __syncthreads();

        // S = Q @ K^T  (4x4 per thread)
        float s_[4][4];
#pragma unroll
        for (int i = 0; i < 4; i++)
#pragma unroll
            for (int j = 0; j < 4; j++) s_[i][j] = 0.f;

#pragma unroll 16
        for (int kk = 0; kk < 64; kk++) {
            const float* qr = &Qt[kk * QP + (ty << 2)];
            const float* kr = &KtPs[kk * QP + (tx << 2)];
            float a0 = qr[0], a1 = qr[1], a2 = qr[2], a3 = qr[3];
            float b0 = kr[0], b1 = kr[1], b2 = kr[2], b3 = kr[3];
            s_[0][0] += a0 * b0; s_[0][1] += a0 * b1; s_[0][2] += a0 * b2; s_[0][3] += a0 * b3;
            s_[1][0] += a1 * b0; s_[1][1] += a1 * b1; s_[1][2] += a1 * b2; s_[1][3] += a1 * b3;
            s_[2][0] += a2 * b0; s_[2][1] += a2 * b1; s_[2][2] += a2 * b2; s_[2][3] += a2 * b3;
            s_[3][0] += a3 * b0; s_[3][1] += a3 * b1; s_[3][2] += a3 * b2; s_[3][3] += a3 * b3;
        }
        __syncthreads();   // done reading K tile; about to overwrite it with P

        // scale + causal mask, write P (raw) into KtPs as [m][n]
        const int qrow = qt * 64 + ty * 4;
        const int krow = kt * 64 + tx * 4;
#pragma unroll
        for (int i = 0; i < 4; i++)
#pragma unroll
            for (int j = 0; j < 4; j++) {
                float v = s_[i][j] * 0.125f;    // 1/sqrt(64)
                if (kt == qt && (qrow + i) < (krow + j)) v = -1e30f;
                KtPs[(ty * 4 + i) * QP + (tx * 4 + j)] = v;
            }
        __syncthreads();

        // online softmax per row (64 threads, one row each)
        if (tid < 64) {
            float* Pr = KtPs + tid * QP;
            float mx = -1e30f;
#pragma unroll 16
            for (int n = 0; n < 64; n++) mx = fmaxf(mx, Pr[n]);
            float mold = row_m[tid];
            float newm = fmaxf(mold, mx);
            float alpha = __expf(mold - newm);
            float ssum = 0.f;
#pragma unroll 16
            for (int n = 0; n < 64; n++) {
                float e = __expf(Pr[n] - newm);
                Pr[n] = e;
                ssum += e;
            }
            row_m[tid] = newm;
            row_l[tid] = row_l[tid] * alpha + ssum;
            row_a[tid] = alpha;
        }
        __syncthreads();

        // O = O*alpha + P @ V
        float al[4];
#pragma unroll
        for (int i = 0; i < 4; i++) al[i] = row_a[ty * 4 + i];
#pragma unroll
        for (int i = 0; i < 4; i++)
#pragma unroll
            for (int j = 0; j < 4; j++) o[i][j] *= al[i];

#pragma unroll 8
        for (int n = 0; n < 64; n++) {
            float p0 = KtPs[(ty * 4 + 0) * QP + n];
            float p1 = KtPs[(ty * 4 + 1) * QP + n];
            float p2 = KtPs[(ty * 4 + 2) * QP + n];
            float p3 = KtPs[(ty * 4 + 3) * QP + n];
            float4 vv = *(const float4*)&Vs[n * VP + (tx << 2)];
            o[0][0] += p0 * vv.x; o[0][1] += p0 * vv.y; o[0][2] += p0 * vv.z; o[0][3] += p0 * vv.w;
            o[1][0] += p1 * vv.x; o[1][1] += p1 * vv.y; o[1][2] += p1 * vv.z; o[1][3] += p1 * vv.w;
            o[2][0] += p2 * vv.x; o[2][1] += p2 * vv.y; o[2][2] += p2 * vv.z; o[2][3] += p2 * vv.w;
            o[3][0] += p3 * vv.x; o[3][1] += p3 * vv.y; o[3][2] += p3 * vv.z; o[3][3] += p3 * vv.w;
        }
    }

    // epilogue: normalize and write (b, s, h, d) into AO (4096 x 2048)
    float* Ob = AO + ((size_t)(b * PS + qt * 64)) * (PH * PHD) + h * PHD;
#pragma unroll
    for (int i = 0; i < 4; i++) {
        int m = ty * 4 + i;
        float inv = 1.0f / row_l[m];
        float4 v = make_float4(o[i][0] * inv, o[i][1] * inv, o[i][2] * inv, o[i][3] * inv);
        *(float4*)(Ob + (size_t)m * (PH * PHD) + (tx << 2)) = v;
    }
}

// ---------------------------------------------------------------------------
// Launch
// ---------------------------------------------------------------------------
extern "C" void kernel_launch(void* const* d_in, const int* in_sizes, int n_in,
                              void* d_out, int out_size)
{
    (void)in_sizes; (void)n_in; (void)out_size;
    const float* x  = (const float*)d_in[0];
    const float* cs = (const float*)d_in[1];
    const float* sn = (const float*)d_in[2];
    const float* Wq = (const float*)d_in[3];
    const float* Wk = (const float*)d_in[4];
    const float* Wv = (const float*)d_in[5];
    const float* Wo = (const float*)d_in[6];
    float* out = (float*)d_out;

    float *Qp, *Kp, *Vp, *AOp;
    cudaGetSymbolAddress((void**)&Qp, g_Q);
    cudaGetSymbolAddress((void**)&Kp, g_K);
    cudaGetSymbolAddress((void**)&Vp, g_V);
    cudaGetSymbolAddress((void**)&AOp, g_AO);

    // QKV projections
    sgemm_nt<<<dim3(PD / GBN, PM / GBM), 256>>>(x, Wq, Qp, PM, PD, PD);
    sgemm_nt<<<dim3((PKV * PHD) / GBN, PM / GBM), 256>>>(x, Wk, Kp, PM, PKV * PHD, PD);
    sgemm_nt<<<dim3((PKV * PHD) / GBN, PM / GBM), 256>>>(x, Wv, Vp, PM, PKV * PHD, PD);

    // RoPE on Q and K
    rope_kernel<<<(PM * PH * 32) / 256, 256>>>(Qp, cs, sn, PH);
    rope_kernel<<<(PM * PKV * 32) / 256, 256>>>(Kp, cs, sn, PKV);

    // causal flash attention
    cudaFuncSetAttribute(flash_attn, cudaFuncAttributeMaxDynamicSharedMemorySize, FA_SMEM);
    flash_attn<<<dim3(PS / 64, PH, PB), 256, FA_SMEM>>>(Qp, Kp, Vp, AOp);

    // output projection
    sgemm_nt<<<dim3(PD / GBN, PM / GBM), 256>>>(AOp, Wo, out, PM, PD, PD);
}

// round 2
// speedup vs baseline: 1.4129x; 1.4129x over previous
#include <cuda_runtime.h>
#include <cstdint>
#include <cstdio>

// Problem constants
#define PB 2
#define PS 2048
#define PD 2048
#define PH 32
#define PKV 8
#define PHD 64
#define PM (PB * PS)          // 4096 rows of x
#define PG (PH / PKV)         // 4

// ---------------------------------------------------------------------------
// Scratch (device globals; no runtime allocation allowed)
// ---------------------------------------------------------------------------
__device__ float g_Q[(size_t)PM * PD];             // (4096, 2048)  32MB
__device__ float g_K[(size_t)PM * (PKV * PHD)];    // (4096, 512)    8MB
__device__ float g_V[(size_t)PM * (PKV * PHD)];    // (4096, 512)    8MB
__device__ float g_AO[(size_t)PM * PD];            // (4096, 2048)  32MB

// ---------------------------------------------------------------------------
// TF32 helpers
// ---------------------------------------------------------------------------
__device__ __forceinline__ uint32_t f2tf32(float x) {
    uint32_t r;
    asm("cvt.rna.tf32.f32 %0, %1;" : "=r"(r) : "f"(x));
    return r;
}

__device__ __forceinline__ void mma_tf32(float* d, const uint32_t* a, const uint32_t* b) {
    asm volatile(
        "mma.sync.aligned.m16n8k8.row.col.f32.tf32.tf32.f32 "
        "{%0,%1,%2,%3}, {%4,%5,%6,%7}, {%8,%9}, {%0,%1,%2,%3};"
        : "+f"(d[0]), "+f"(d[1]), "+f"(d[2]), "+f"(d[3])
        : "r"(a[0]), "r"(a[1]), "r"(a[2]), "r"(a[3]),
          "r"(b[0]), "r"(b[1]));
}

// ---------------------------------------------------------------------------
// TF32 tensor-core GEMM (NT): C[M,N] = A[M,K] @ B[N,K]^T (row-major, K contig)
// 128x128 block tile, BK=16, 256 threads = 8 warps (2 x 4), warp tile 64x32.
// mma.m16n8k8: per warp 4 m-subtiles x 4 n-subtiles.
// ---------------------------------------------------------------------------
#define SST 17   // smem row stride (floats) -> <=2-way LDS conflicts

__global__ __launch_bounds__(256, 2)
void mma_gemm_nt(const float* __restrict__ A, const float* __restrict__ B,
                 float* __restrict__ C, int M, int N, int K)
{
    __shared__ uint32_t As[128 * SST];   // [m][k] tf32
    __shared__ uint32_t Bs[128 * SST];   // [n][k] tf32

    const int tid  = threadIdx.x;
    const int lane = tid & 31;
    const int warp = tid >> 5;
    const int g    = lane >> 2;          // group id (row within 8)
    const int tig  = lane & 3;           // thread in group (col within 4)
    const int warp_m = warp >> 2;        // 0..1  -> m offset *64
    const int warp_n = warp & 3;         // 0..3  -> n offset *32
    const int bm = blockIdx.y;
    const int bn = blockIdx.x;

    const float* Ab = A + (size_t)bm * 128 * K;
    const float* Bb = B + (size_t)bn * 128 * K;

    float acc[4][4][4];
#pragma unroll
    for (int i = 0; i < 4; i++)
#pragma unroll
        for (int j = 0; j < 4; j++)
#pragma unroll
            for (int r = 0; r < 4; r++) acc[i][j][r] = 0.f;

    for (int k0 = 0; k0 < K; k0 += 16) {
        // stage 128x16 of A and B into smem as tf32
#pragma unroll
        for (int r = 0; r < 2; r++) {
            int e   = tid + 256 * r;       // 0..511
            int row = e >> 2;              // 0..127
            int ks  = (e & 3) << 2;        // 0,4,8,12
            float4 va = *(const float4*)(Ab + (size_t)row * K + k0 + ks);
            As[row * SST + ks + 0] = f2tf32(va.x);
            As[row * SST + ks + 1] = f2tf32(va.y);
            As[row * SST + ks + 2] = f2tf32(va.z);
            As[row * SST + ks + 3] = f2tf32(va.w);
            float4 vb = *(const float4*)(Bb + (size_t)row * K + k0 + ks);
            Bs[row * SST + ks + 0] = f2tf32(vb.x);
            Bs[row * SST + ks + 1] = f2tf32(vb.y);
            Bs[row * SST + ks + 2] = f2tf32(vb.z);
            Bs[row * SST + ks + 3] = f2tf32(vb.w);
        }
        __syncthreads();

#pragma unroll
        for (int ks = 0; ks < 16; ks += 8) {
            uint32_t afr[4][4], bfr[4][2];
#pragma unroll
            for (int i = 0; i < 4; i++) {
                int row = warp_m * 64 + i * 16;
                afr[i][0] = As[(row + g)     * SST + ks + tig];
                afr[i][1] = As[(row + g + 8) * SST + ks + tig];
                afr[i][2] = As[(row + g)     * SST + ks + tig + 4];
                afr[i][3] = As[(row + g + 8) * SST + ks + tig + 4];
            }
#pragma unroll
            for (int j = 0; j < 4; j++) {
                int col = warp_n * 32 + j * 8;
                bfr[j][0] = Bs[(col + g) * SST + ks + tig];
                bfr[j][1] = Bs[(col + g) * SST + ks + tig + 4];
            }
#pragma unroll
            for (int i = 0; i < 4; i++)
#pragma unroll
                for (int j = 0; j < 4; j++)
                    mma_tf32(acc[i][j], afr[i], bfr[j]);
        }
        __syncthreads();
    }

    // epilogue
#pragma unroll
    for (int i = 0; i < 4; i++) {
        int row0 = bm * 128 + warp_m * 64 + i * 16 + g;
#pragma unroll
        for (int j = 0; j < 4; j++) {
            int col = bn * 128 + warp_n * 32 + j * 8 + 2 * tig;
            *(float2*)(C + (size_t)row0 * N + col)       = make_float2(acc[i][j][0], acc[i][j][1]);
            *(float2*)(C + (size_t)(row0 + 8) * N + col) = make_float2(acc[i][j][2], acc[i][j][3]);
        }
    }
}

// ---------------------------------------------------------------------------
// RoPE (in place).  X viewed as (PM, nheads, 64); pairs (d, d+32), d<32.
// ---------------------------------------------------------------------------
__global__ void rope_kernel(float* __restrict__ X, const float* __restrict__ cs,
                            const float* __restrict__ sn, int nheads)
{
    int i = blockIdx.x * blockDim.x + threadIdx.x;
    int total = PM * nheads * 32;
    if (i >= total) return;
    int d   = i & 31;
    int h   = (i >> 5) % nheads;
    int row = i / (32 * nheads);
    int s   = row & (PS - 1);
    float c = cs[s * 32 + d];
    float sv = sn[s * 32 + d];
    float* base = X + ((size_t)row * nheads + h) * 64;
    float x1 = base[d];
    float x2 = base[d + 32];
    base[d]      = x1 * c - x2 * sv;
    base[d + 32] = x1 * sv + x2 * c;
}

// ---------------------------------------------------------------------------
// Causal flash attention, fp32 (unchanged from R1 baseline).
// ---------------------------------------------------------------------------
#define QP 65
#define VP 68
#define FA_SMEM ((2 * 64 * QP + 64 * VP + 3 * 64) * 4)

__global__ __launch_bounds__(256, 3)
void flash_attn(const float* __restrict__ Q, const float* __restrict__ Kg,
                const float* __restrict__ Vg, float* __restrict__ AO)
{
    extern __shared__ float sm[];
    float* Qt    = sm;
    float* KtPs  = Qt + 64 * QP;
    float* Vs    = KtPs + 64 * QP;
    float* row_m = Vs + 64 * VP;
    float* row_l = row_m + 64;
    float* row_a = row_l + 64;

    const int qt = blockIdx.x;
    const int h  = blockIdx.y;
    const int b  = blockIdx.z;
    const int kvh = h >> 2;
    const int tid = threadIdx.x;
    const int tx = tid & 15;
    const int ty = tid >> 4;

    const float* Qbase = Q + ((size_t)(b * PS + qt * 64)) * (PH * PHD) + h * PHD;

#pragma unroll
    for (int r = 0; r < 4; r++) {
        int e   = tid + 256 * r;
        int row = e >> 4;
        int ds  = (e & 15) << 2;
        float4 v = *(const float4*)(Qbase + (size_t)row * (PH * PHD) + ds);
        Qt[(ds + 0) * QP + row] = v.x;
        Qt[(ds + 1) * QP + row] = v.y;
        Qt[(ds + 2) * QP + row] = v.z;
        Qt[(ds + 3) * QP + row] = v.w;
    }
    if (tid < 64) { row_m[tid] = -1e30f; row_l[tid] = 0.f; }

    float o[4][4];
#pragma unroll
    for (int i = 0; i < 4; i++)
#pragma unroll
        for (int j = 0; j < 4; j++) o[i][j] = 0.f;

    for (int kt = 0; kt <= qt; kt++) {
        const float* Kbase = Kg + ((size_t)(b * PS + kt * 64)) * (PKV * PHD) + kvh * PHD;
        const float* Vbase = Vg + ((size_t)(b * PS + kt * 64)) * (PKV * PHD) + kvh * PHD;

        __syncthreads();

#pragma unroll
        for (int r = 0; r < 4; r++) {
            int e   = tid + 256 * r;
            int row = e >> 4;
            int ds  = (e & 15) << 2;
            float4 kv4 = *(const float4*)(Kbase + (size_t)row * (PKV * PHD) + ds);
            KtPs[(ds + 0) * QP + row] = kv4.x;
            KtPs[(ds + 1) * QP + row] = kv4.y;
            KtPs[(ds + 2) * QP + row] = kv4.z;
            KtPs[(ds + 3) * QP + row] = kv4.w;
            float4 vv4 = *(const float4*)(Vbase + (size_t)row * (PKV * PHD) + ds);
            *(float4*)&Vs[row * VP + ds] = vv4;
        }
        __syncthreads();

        float s_[4][4];
#pragma unroll
        for (int i = 0; i < 4; i++)
#pragma unroll
            for (int j = 0; j < 4; j++) s_[i][j] = 0.f;

#pragma unroll 16
        for (int kk = 0; kk < 64; kk++) {
            const float* qr = &Qt[kk * QP + (ty << 2)];
            const float* kr = &KtPs[kk * QP + (tx << 2)];
            float a0 = qr[0], a1 = qr[1], a2 = qr[2], a3 = qr[3];
            float b0 = kr[0], b1 = kr[1], b2 = kr[2], b3 = kr[3];
            s_[0][0] += a0 * b0; s_[0][1] += a0 * b1; s_[0][2] += a0 * b2; s_[0][3] += a0 * b3;
            s_[1][0] += a1 * b0; s_[1][1] += a1 * b1; s_[1][2] += a1 * b2; s_[1][3] += a1 * b3;
            s_[2][0] += a2 * b0; s_[2][1] += a2 * b1; s_[2][2] += a2 * b2; s_[2][3] += a2 * b3;
            s_[3][0] += a3 * b0; s_[3][1] += a3 * b1; s_[3][2] += a3 * b2; s_[3][3] += a3 * b3;
        }
        __syncthreads();

        const int qrow = qt * 64 + ty * 4;
        const int krow = kt * 64 + tx * 4;
#pragma unroll
        for (int i = 0; i < 4; i++)
#pragma unroll
            for (int j = 0; j < 4; j++) {
                float v = s_[i][j] * 0.125f;
                if (kt == qt && (qrow + i) < (krow + j)) v = -1e30f;
                KtPs[(ty * 4 + i) * QP + (tx * 4 + j)] = v;
            }
        __syncthreads();

        if (tid < 64) {
            float* Pr = KtPs + tid * QP;
            float mx = -1e30f;
#pragma unroll 16
            for (int n = 0; n < 64; n++) mx = fmaxf(mx, Pr[n]);
            float mold = row_m[tid];
            float newm = fmaxf(mold, mx);
            float alpha = __expf(mold - newm);
            float ssum = 0.f;
#pragma unroll 16
            for (int n = 0; n < 64; n++) {
                float e = __expf(Pr[n] - newm);
                Pr[n] = e;
                ssum += e;
            }
            row_m[tid] = newm;
            row_l[tid] = row_l[tid] * alpha + ssum;
            row_a[tid] = alpha;
        }
        __syncthreads();

        float al[4];
#pragma unroll
        for (int i = 0; i < 4; i++) al[i] = row_a[ty * 4 + i];
#pragma unroll
        for (int i = 0; i < 4; i++)
#pragma unroll
            for (int j = 0; j < 4; j++) o[i][j] *= al[i];

#pragma unroll 8
        for (int n = 0; n < 64; n++) {
            float p0 = KtPs[(ty * 4 + 0) * QP + n];
            float p1 = KtPs[(ty * 4 + 1) * QP + n];
            float p2 = KtPs[(ty * 4 + 2) * QP + n];
            float p3 = KtPs[(ty * 4 + 3) * QP + n];
            float4 vv = *(const float4*)&Vs[n * VP + (tx << 2)];
            o[0][0] += p0 * vv.x; o[0][1] += p0 * vv.y; o[0][2] += p0 * vv.z; o[0][3] += p0 * vv.w;
            o[1][0] += p1 * vv.x; o[1][1] += p1 * vv.y; o[1][2] += p1 * vv.z; o[1][3] += p1 * vv.w;
            o[2][0] += p2 * vv.x; o[2][1] += p2 * vv.y; o[2][2] += p2 * vv.z; o[2][3] += p2 * vv.w;
            o[3][0] += p3 * vv.x; o[3][1] += p3 * vv.y; o[3][2] += p3 * vv.z; o[3][3] += p3 * vv.w;
        }
    }

    float* Ob = AO + ((size_t)(b * PS + qt * 64)) * (PH * PHD) + h * PHD;
#pragma unroll
    for (int i = 0; i < 4; i++) {
        int m = ty * 4 + i;
        float inv = 1.0f / row_l[m];
        float4 v = make_float4(o[i][0] * inv, o[i][1] * inv, o[i][2] * inv, o[i][3] * inv);
        *(float4*)(Ob + (size_t)m * (PH * PHD) + (tx << 2)) = v;
    }
}

// ---------------------------------------------------------------------------
// Launch
// ---------------------------------------------------------------------------
extern "C" void kernel_launch(void* const* d_in, const int* in_sizes, int n_in,
                              void* d_out, int out_size)
{
    (void)in_sizes; (void)n_in; (void)out_size;
    const float* x  = (const float*)d_in[0];
    const float* cs = (const float*)d_in[1];
    const float* sn = (const float*)d_in[2];
    const float* Wq = (const float*)d_in[3];
    const float* Wk = (const float*)d_in[4];
    const float* Wv = (const float*)d_in[5];
    const float* Wo = (const float*)d_in[6];
    float* out = (float*)d_out;

    float *Qp, *Kp, *Vp, *AOp;
    cudaGetSymbolAddress((void**)&Qp, g_Q);
    cudaGetSymbolAddress((void**)&Kp, g_K);
    cudaGetSymbolAddress((void**)&Vp, g_V);
    cudaGetSymbolAddress((void**)&AOp, g_AO);

    // QKV projections (tf32 tensor cores)
    mma_gemm_nt<<<dim3(PD / 128, PM / 128), 256>>>(x, Wq, Qp, PM, PD, PD);
    mma_gemm_nt<<<dim3((PKV * PHD) / 128, PM / 128), 256>>>(x, Wk, Kp, PM, PKV * PHD, PD);
    mma_gemm_nt<<<dim3((PKV * PHD) / 128, PM / 128), 256>>>(x, Wv, Vp, PM, PKV * PHD, PD);

    // RoPE on Q and K
    rope_kernel<<<(PM * PH * 32) / 256, 256>>>(Qp, cs, sn, PH);
    rope_kernel<<<(PM * PKV * 32) / 256, 256>>>(Kp, cs, sn, PKV);

    // causal flash attention (fp32)
    cudaFuncSetAttribute(flash_attn, cudaFuncAttributeMaxDynamicSharedMemorySize, FA_SMEM);
    flash_attn<<<dim3(PS / 64, PH, PB), 256, FA_SMEM>>>(Qp, Kp, Vp, AOp);

    // output projection (tf32 tensor cores)
    mma_gemm_nt<<<dim3(PD / 128, PM / 128), 256>>>(AOp, Wo, out, PM, PD, PD);
}

// round 4
// speedup vs baseline: 2.2712x; 1.6075x over previous
#include <cuda_runtime.h>
#include <cstdint>
#include <cstdio>

// Problem constants
#define PB 2
#define PS 2048
#define PD 2048
#define PH 32
#define PKV 8
#define PHD 64
#define PM (PB * PS)          // 4096 rows of x
#define PG (PH / PKV)         // 4

// ---------------------------------------------------------------------------
// Scratch (device globals; no runtime allocation allowed)
// ---------------------------------------------------------------------------
__device__ float g_Q[(size_t)PM * PD];             // (4096, 2048)  32MB
__device__ float g_K[(size_t)PM * (PKV * PHD)];    // (4096, 512)    8MB
__device__ float g_V[(size_t)PM * (PKV * PHD)];    // (4096, 512)    8MB
__device__ float g_AO[(size_t)PM * PD];            // (4096, 2048)  32MB

// ---------------------------------------------------------------------------
// TF32 helpers
// ---------------------------------------------------------------------------
__device__ __forceinline__ uint32_t f2tf32(float x) {
    uint32_t r;
    asm("cvt.rna.tf32.f32 %0, %1;" : "=r"(r) : "f"(x));
    return r;
}

__device__ __forceinline__ void mma_tf32(float* d, const uint32_t* a, const uint32_t* b) {
    asm volatile(
        "mma.sync.aligned.m16n8k8.row.col.f32.tf32.tf32.f32 "
        "{%0,%1,%2,%3}, {%4,%5,%6,%7}, {%8,%9}, {%0,%1,%2,%3};"
        : "+f"(d[0]), "+f"(d[1]), "+f"(d[2]), "+f"(d[3])
        : "r"(a[0]), "r"(a[1]), "r"(a[2]), "r"(a[3]),
          "r"(b[0]), "r"(b[1]));
}

// ---------------------------------------------------------------------------
// TF32 tensor-core GEMM (NT): C[M,N] = A[M,K] @ B[N,K]^T (row-major, K contig)
// 128x128 block tile, BK=16, 256 threads = 8 warps (2 x 4), warp tile 64x32.
// Double-buffered smem with register prefetch of the next k-tile.
// ---------------------------------------------------------------------------
#define SST 17   // smem row stride (floats) -> <=2-way LDS conflicts

__global__ __launch_bounds__(256, 2)
void mma_gemm_nt(const float* __restrict__ A, const float* __restrict__ B,
                 float* __restrict__ C, int M, int N, int K)
{
    __shared__ uint32_t As[2][128 * SST];   // [m][k] tf32
    __shared__ uint32_t Bs[2][128 * SST];   // [n][k] tf32

    const int tid  = threadIdx.x;
    const int lane = tid & 31;
    const int warp = tid >> 5;
    const int g    = lane >> 2;
    const int tig  = lane & 3;
    const int warp_m = warp >> 2;        // 0..1  -> m offset *64
    const int warp_n = warp & 3;         // 0..3  -> n offset *32
    const int bm = blockIdx.y;
    const int bn = blockIdx.x;

    const float* Ab = A + (size_t)bm * 128 * K;
    const float* Bb = B + (size_t)bn * 128 * K;

    // per-thread load coordinates (2 float4 each for A and B)
    int lrow[2], lks[2];
#pragma unroll
    for (int r = 0; r < 2; r++) {
        int e = tid + 256 * r;
        lrow[r] = e >> 2;
        lks[r]  = (e & 3) << 2;
    }

    float acc[4][4][4];
#pragma unroll
    for (int i = 0; i < 4; i++)
#pragma unroll
        for (int j = 0; j < 4; j++)
#pragma unroll
            for (int r = 0; r < 4; r++) acc[i][j][r] = 0.f;

    const int T = K / 16;
    float4 pa[2], pb[2];

    // prologue: prefetch tile 0
#pragma unroll
    for (int r = 0; r < 2; r++) {
        pa[r] = *(const float4*)(Ab + (size_t)lrow[r] * K + lks[r]);
        pb[r] = *(const float4*)(Bb + (size_t)lrow[r] * K + lks[r]);
    }

    for (int t = 0; t < T; t++) {
        const int buf = t & 1;
        // store prefetched tile into smem (tf32)
#pragma unroll
        for (int r = 0; r < 2; r++) {
            uint32_t* ap = &As[buf][lrow[r] * SST + lks[r]];
            ap[0] = f2tf32(pa[r].x); ap[1] = f2tf32(pa[r].y);
            ap[2] = f2tf32(pa[r].z); ap[3] = f2tf32(pa[r].w);
            uint32_t* bp = &Bs[buf][lrow[r] * SST + lks[r]];
            bp[0] = f2tf32(pb[r].x); bp[1] = f2tf32(pb[r].y);
            bp[2] = f2tf32(pb[r].z); bp[3] = f2tf32(pb[r].w);
        }
        __syncthreads();

        // prefetch next tile while computing
        if (t + 1 < T) {
            int k0 = (t + 1) * 16;
#pragma unroll
            for (int r = 0; r < 2; r++) {
                pa[r] = *(const float4*)(Ab + (size_t)lrow[r] * K + k0 + lks[r]);
                pb[r] = *(const float4*)(Bb + (size_t)lrow[r] * K + k0 + lks[r]);
            }
        }

#pragma unroll
        for (int ks = 0; ks < 16; ks += 8) {
            uint32_t afr[4][4], bfr[4][2];
#pragma unroll
            for (int i = 0; i < 4; i++) {
                int row = warp_m * 64 + i * 16;
                afr[i][0] = As[buf][(row + g)     * SST + ks + tig];
                afr[i][1] = As[buf][(row + g + 8) * SST + ks + tig];
                afr[i][2] = As[buf][(row + g)     * SST + ks + tig + 4];
                afr[i][3] = As[buf][(row + g + 8) * SST + ks + tig + 4];
            }
#pragma unroll
            for (int j = 0; j < 4; j++) {
                int col = warp_n * 32 + j * 8;
                bfr[j][0] = Bs[buf][(col + g) * SST + ks + tig];
                bfr[j][1] = Bs[buf][(col + g) * SST + ks + tig + 4];
            }
#pragma unroll
            for (int i = 0; i < 4; i++)
#pragma unroll
                for (int j = 0; j < 4; j++)
                    mma_tf32(acc[i][j], afr[i], bfr[j]);
        }
    }

    // epilogue
#pragma unroll
    for (int i = 0; i < 4; i++) {
        int row0 = bm * 128 + warp_m * 64 + i * 16 + g;
#pragma unroll
        for (int j = 0; j < 4; j++) {
            int col = bn * 128 + warp_n * 32 + j * 8 + 2 * tig;
            *(float2*)(C + (size_t)row0 * N + col)       = make_float2(acc[i][j][0], acc[i][j][1]);
            *(float2*)(C + (size_t)(row0 + 8) * N + col) = make_float2(acc[i][j][2], acc[i][j][3]);
        }
    }
}

// ---------------------------------------------------------------------------
// RoPE (in place).  X viewed as (PM, nheads, 64); pairs (d, d+32), d<32.
// ---------------------------------------------------------------------------
__global__ void rope_kernel(float* __restrict__ X, const float* __restrict__ cs,
                            const float* __restrict__ sn, int nheads)
{
    int i = blockIdx.x * blockDim.x + threadIdx.x;
    int total = PM * nheads * 32;
    if (i >= total) return;
    int d   = i & 31;
    int h   = (i >> 5) % nheads;
    int row = i / (32 * nheads);
    int s   = row & (PS - 1);
    float c = cs[s * 32 + d];
    float sv = sn[s * 32 + d];
    float* base = X + ((size_t)row * nheads + h) * 64;
    float x1 = base[d];
    float x2 = base[d + 32];
    base[d]      = x1 * c - x2 * sv;
    base[d + 32] = x1 * sv + x2 * c;
}

// ---------------------------------------------------------------------------
// Causal flash attention, tf32 tensor cores.
// grid (S/64, H, B), 256 threads = 8 warps in a 4x2 grid.
// Per tile: S = Q@K^T via MMA -> smem, 256-thread online softmax (4 thr/row),
// P (tf32) @ V via MMA accumulated in registers.
// ---------------------------------------------------------------------------
#define AQP 68
#define FA_SMEM ((4 * 64 * AQP + 3 * 64) * 4)

__global__ __launch_bounds__(256, 2)
void flash_attn_mma(const float* __restrict__ Q, const float* __restrict__ Kg,
                    const float* __restrict__ Vg, float* __restrict__ AO)
{
    extern __shared__ float smf[];
    uint32_t* Qs = (uint32_t*)smf;                 // [64][AQP] tf32  [m][d]
    uint32_t* Ks = Qs + 64 * AQP;                  // [64][AQP] tf32  [n][d]
    uint32_t* Vs = Ks + 64 * AQP;                  // [64][AQP] tf32  [k][d]
    float*    Ssf = (float*)(Vs + 64 * AQP);       // [64][AQP] scores / P
    uint32_t* Ssu = (uint32_t*)Ssf;
    float* row_m = Ssf + 64 * AQP;
    float* row_l = row_m + 64;
    float* row_a = row_l + 64;

    const int qt = blockIdx.x;
    const int h  = blockIdx.y;
    const int b  = blockIdx.z;
    const int kvh = h >> 2;
    const int tid  = threadIdx.x;
    const int lane = tid & 31;
    const int warp = tid >> 5;
    const int g    = lane >> 2;
    const int tig  = lane & 3;
    const int warp_m = warp >> 1;    // 0..3 -> 16 rows each
    const int warp_n = warp & 1;     // 0..1 -> 32 cols each

    const float* Qbase = Q + ((size_t)(b * PS + qt * 64)) * (PH * PHD) + h * PHD;

    // load Q tile (fp32 -> tf32), layout [m][d]
#pragma unroll
    for (int r = 0; r < 4; r++) {
        int e   = tid + 256 * r;
        int row = e >> 4;
        int ds  = (e & 15) << 2;
        float4 v = *(const float4*)(Qbase + (size_t)row * (PH * PHD) + ds);
        uint4 u = make_uint4(f2tf32(v.x), f2tf32(v.y), f2tf32(v.z), f2tf32(v.w));
        *(uint4*)&Qs[row * AQP + ds] = u;
    }
    if (tid < 64) { row_m[tid] = -1e30f; row_l[tid] = 0.f; }

    float o[4][4];   // [n-subtile][reg]: rows g,g+8 x col pairs
#pragma unroll
    for (int j = 0; j < 4; j++)
#pragma unroll
        for (int r = 0; r < 4; r++) o[j][r] = 0.f;

    for (int kt = 0; kt <= qt; kt++) {
        const float* Kbase = Kg + ((size_t)(b * PS + kt * 64)) * (PKV * PHD) + kvh * PHD;
        const float* Vbase = Vg + ((size_t)(b * PS + kt * 64)) * (PKV * PHD) + kvh * PHD;

        __syncthreads();   // prior PV reads of Ss/Vs done; Q stores done (iter 0)

        // load K and V tiles (fp32 -> tf32)
#pragma unroll
        for (int r = 0; r < 4; r++) {
            int e   = tid + 256 * r;
            int row = e >> 4;
            int ds  = (e & 15) << 2;
            float4 kv = *(const float4*)(Kbase + (size_t)row * (PKV * PHD) + ds);
            *(uint4*)&Ks[row * AQP + ds] =
                make_uint4(f2tf32(kv.x), f2tf32(kv.y), f2tf32(kv.z), f2tf32(kv.w));
            float4 vv = *(const float4*)(Vbase + (size_t)row * (PKV * PHD) + ds);
            *(uint4*)&Vs[row * AQP + ds] =
                make_uint4(f2tf32(vv.x), f2tf32(vv.y), f2tf32(vv.z), f2tf32(vv.w));
        }
        __syncthreads();

        // S = Q @ K^T : warp tile 16 rows x 32 cols, 4 n-subtiles, k = d = 64
        float s_[4][4];
#pragma unroll
        for (int j = 0; j < 4; j++)
#pragma unroll
            for (int r = 0; r < 4; r++) s_[j][r] = 0.f;

        const int rowbase = warp_m * 16;
        const int colbase = warp_n * 32;
#pragma unroll
        for (int ks = 0; ks < 64; ks += 8) {
            uint32_t afr[4], bfr[4][2];
            afr[0] = Qs[(rowbase + g)     * AQP + ks + tig];
            afr[1] = Qs[(rowbase + g + 8) * AQP + ks + tig];
            afr[2] = Qs[(rowbase + g)     * AQP + ks + tig + 4];
            afr[3] = Qs[(rowbase + g + 8) * AQP + ks + tig + 4];
#pragma unroll
            for (int j = 0; j < 4; j++) {
                int col = colbase + j * 8;
                bfr[j][0] = Ks[(col + g) * AQP + ks + tig];
                bfr[j][1] = Ks[(col + g) * AQP + ks + tig + 4];
            }
#pragma unroll
            for (int j = 0; j < 4; j++)
                mma_tf32(s_[j], afr, bfr[j]);
        }

        // scale + causal mask, write S to smem
        const int qr0 = qt * 64 + rowbase + g;
#pragma unroll
        for (int j = 0; j < 4; j++) {
            int c0 = colbase + j * 8 + 2 * tig;
            int kc0 = kt * 64 + c0;
            float v0 = s_[j][0] * 0.125f, v1 = s_[j][1] * 0.125f;
            float v2 = s_[j][2] * 0.125f, v3 = s_[j][3] * 0.125f;
            if (kc0     > qr0)     v0 = -1e30f;
            if (kc0 + 1 > qr0)     v1 = -1e30f;
            if (kc0     > qr0 + 8) v2 = -1e30f;
            if (kc0 + 1 > qr0 + 8) v3 = -1e30f;
            *(float2*)&Ssf[(rowbase + g)     * AQP + c0] = make_float2(v0, v1);
            *(float2*)&Ssf[(rowbase + g + 8) * AQP + c0] = make_float2(v2, v3);
        }
        __syncthreads();

        // online softmax: 64 rows x 4 threads, 16 cols each; write P back as tf32
        {
            const int row = tid >> 2;
            const int p   = tid & 3;
            float* Pr = Ssf + row * AQP + p * 16;
            float mx = -1e30f;
#pragma unroll
            for (int n = 0; n < 16; n++) mx = fmaxf(mx, Pr[n]);
            mx = fmaxf(mx, __shfl_xor_sync(0xffffffffu, mx, 1));
            mx = fmaxf(mx, __shfl_xor_sync(0xffffffffu, mx, 2));
            float mold = row_m[row];
            float newm = fmaxf(mold, mx);
            float ssum = 0.f;
            uint32_t* Pu = Ssu + row * AQP + p * 16;
#pragma unroll
            for (int n = 0; n < 16; n++) {
                float e = __expf(Pr[n] - newm);
                ssum += e;
                Pu[n] = f2tf32(e);
            }
            ssum += __shfl_xor_sync(0xffffffffu, ssum, 1);
            ssum += __shfl_xor_sync(0xffffffffu, ssum, 2);
            if (p == 0) {
                float alpha = __expf(mold - newm);
                row_m[row] = newm;
                row_l[row] = row_l[row] * alpha + ssum;
                row_a[row] = alpha;
            }
        }
        __syncthreads();

        // O = O*alpha + P @ V   (warp tile 16 rows x 32 d-cols, k = 64 keys)
        float al0 = row_a[rowbase + g];
        float al1 = row_a[rowbase + g + 8];
#pragma unroll
        for (int j = 0; j < 4; j++) {
            o[j][0] *= al0; o[j][1] *= al0;
            o[j][2] *= al1; o[j][3] *= al1;
        }
#pragma unroll
        for (int ks = 0; ks < 64; ks += 8) {
            uint32_t afr[4], bfr[4][2];
            afr[0] = Ssu[(rowbase + g)     * AQP + ks + tig];
            afr[1] = Ssu[(rowbase + g + 8) * AQP + ks + tig];
            afr[2] = Ssu[(rowbase + g)     * AQP + ks + tig + 4];
            afr[3] = Ssu[(rowbase + g + 8) * AQP + ks + tig + 4];
#pragma unroll
            for (int j = 0; j < 4; j++) {
                int col = colbase + j * 8;
                bfr[j][0] = Vs[(ks + tig)     * AQP + col + g];
                bfr[j][1] = Vs[(ks + tig + 4) * AQP + col + g];
            }
#pragma unroll
            for (int j = 0; j < 4; j++)
                mma_tf32(o[j], afr, bfr[j]);
        }
    }

    // epilogue: normalize and store
    float il0 = 1.0f / row_l[warp_m * 16 + g];
    float il1 = 1.0f / row_l[warp_m * 16 + g + 8];
    float* Ob = AO + ((size_t)(b * PS + qt * 64)) * (PH * PHD) + h * PHD;
    const int r0 = warp_m * 16 + g;
#pragma unroll
    for (int j = 0; j < 4; j++) {
        int c0 = warp_n * 32 + j * 8 + 2 * tig;
        *(float2*)(Ob + (size_t)r0 * (PH * PHD) + c0) =
            make_float2(o[j][0] * il0, o[j][1] * il0);
        *(float2*)(Ob + (size_t)(r0 + 8) * (PH * PHD) + c0) =
            make_float2(o[j][2] * il1, o[j][3] * il1);
    }
}

// ---------------------------------------------------------------------------
// Launch
// ---------------------------------------------------------------------------
extern "C" void kernel_launch(void* const* d_in, const int* in_sizes, int n_in,
                              void* d_out, int out_size)
{
    (void)in_sizes; (void)n_in; (void)out_size;
    const float* x  = (const float*)d_in[0];
    const float* cs = (const float*)d_in[1];
    const float* sn = (const float*)d_in[2];
    const float* Wq = (const float*)d_in[3];
    const float* Wk = (const float*)d_in[4];
    const float* Wv = (const float*)d_in[5];
    const float* Wo = (const float*)d_in[6];
    float* out = (float*)d_out;

    float *Qp, *Kp, *Vp, *AOp;
    cudaGetSymbolAddress((void**)&Qp, g_Q);
    cudaGetSymbolAddress((void**)&Kp, g_K);
    cudaGetSymbolAddress((void**)&Vp, g_V);
    cudaGetSymbolAddress((void**)&AOp, g_AO);

    // QKV projections (tf32 tensor cores, double-buffered)
    mma_gemm_nt<<<dim3(PD / 128, PM / 128), 256>>>(x, Wq, Qp, PM, PD, PD);
    mma_gemm_nt<<<dim3((PKV * PHD) / 128, PM / 128), 256>>>(x, Wk, Kp, PM, PKV * PHD, PD);
    mma_gemm_nt<<<dim3((PKV * PHD) / 128, PM / 128), 256>>>(x, Wv, Vp, PM, PKV * PHD, PD);

    // RoPE on Q and K
    rope_kernel<<<(PM * PH * 32) / 256, 256>>>(Qp, cs, sn, PH);
    rope_kernel<<<(PM * PKV * 32) / 256, 256>>>(Kp, cs, sn, PKV);

    // causal flash attention (tf32 tensor cores)
    cudaFuncSetAttribute(flash_attn_mma, cudaFuncAttributeMaxDynamicSharedMemorySize, FA_SMEM);
    flash_attn_mma<<<dim3(PS / 64, PH, PB), 256, FA_SMEM>>>(Qp, Kp, Vp, AOp);

    // output projection (tf32 tensor cores)
    mma_gemm_nt<<<dim3(PD / 128, PM / 128), 256>>>(AOp, Wo, out, PM, PD, PD);
}